// round 15
// baseline (speedup 1.0000x reference)
#include <cuda_runtime.h>
#include <cuda_fp16.h>
#include <stdint.h>

#define NN 100000
#define NE 800000
#define C  100
#define OC 50
#define NBLK ((NN + 1023) / 1024)

#define TM 128
#define NTILES ((NN + TM - 1) / TM)
#define GEMM_GRID 296            // 2 CTAs per SM
#define GEMM_THREADS 256

// word stride per row: reads touch words 0..55; WS=60 -> conflict-free frags
#define WS 60
#define SA0 0
#define SA1 (TM * WS)                  // 7680
#define SB  (2 * TM * WS)              // 15360
#define SM_WORDS (SB + 104 * WS)       // 21600 words = 86400 B (2 CTAs/SM)

#define CVT_QUADS (NN * 25)

// ---------------- device globals (scratch; zero-init at load) ----------------
__device__ __align__(16) float d_dis[NN];
__device__ __align__(16) __half d_X16[NN * C];   // x pre-converted to fp16
__device__ __align__(16) float  d_G32[NN * C];   // GEMM output (fp32: no cvt in gather)
__device__ __align__(16) __half d_H16[NN * C];   // hidden (fp16: exact GEMM2 A input)
__device__ int d_cnt[NN];      // re-zeroed at tail of gather mode 1 each run
__device__ int d_start[NN];    // after k_fill: END pointers
__device__ int d_csr[NE];
__device__ int d_bsum[NBLK + 1];

// ---------------- PTX helpers (baseline, sm_80+) ----------------
__device__ __forceinline__ void mma_f16(float* d, const uint32_t* a, const uint32_t* b) {
    asm volatile(
        "mma.sync.aligned.m16n8k16.row.col.f32.f16.f16.f32 "
        "{%0,%1,%2,%3}, {%4,%5,%6,%7}, {%8,%9}, {%0,%1,%2,%3};"
        : "+f"(d[0]), "+f"(d[1]), "+f"(d[2]), "+f"(d[3])
        : "r"(a[0]), "r"(a[1]), "r"(a[2]), "r"(a[3]), "r"(b[0]), "r"(b[1]));
}
__device__ __forceinline__ void cp_async8(uint32_t saddr, const void* g, int src_sz) {
    asm volatile("cp.async.ca.shared.global [%0], [%1], 8, %2;"
                 :: "r"(saddr), "l"(g), "r"(src_sz));
}
#define CP_COMMIT() asm volatile("cp.async.commit_group;" ::: "memory")
#define CP_WAIT1()  asm volatile("cp.async.wait_group 1;" ::: "memory")

// ---------------- CSR build ----------------
__global__ void k_degcvt(const int* __restrict__ dst, const float* __restrict__ x) {
    int i = blockIdx.x * blockDim.x + threadIdx.x;
    if (i < NE) atomicAdd(&d_cnt[dst[i]], 1);    // cnt pre-zeroed
    if (i < CVT_QUADS) {
        int r = i / 25, c4 = (i % 25) * 4;
        float4 v = *(const float4*)&x[(size_t)r * C + c4];
        __half2 h0 = __floats2half2_rn(v.x, v.y);
        __half2 h1 = __floats2half2_rn(v.z, v.w);
        uint2 w2;
        w2.x = *reinterpret_cast<uint32_t*>(&h0);
        w2.y = *reinterpret_cast<uint32_t*>(&h1);
        *(uint2*)&d_X16[(size_t)r * C + c4] = w2;
    }
}
__global__ void k_scan1() {   // block-local exclusive scan + dis = rsqrt(cnt+1)
    __shared__ int sh[1024];
    int i = blockIdx.x * 1024 + threadIdx.x;
    int v = (i < NN) ? d_cnt[i] : 0;
    sh[threadIdx.x] = v;
    __syncthreads();
    for (int off = 1; off < 1024; off <<= 1) {
        int t = (threadIdx.x >= off) ? sh[threadIdx.x - off] : 0;
        __syncthreads();
        sh[threadIdx.x] += t;
        __syncthreads();
    }
    if (i < NN) {
        d_start[i] = sh[threadIdx.x] - v;
        d_dis[i] = rsqrtf((float)v + 1.0f);
    }
    if (threadIdx.x == 1023) d_bsum[blockIdx.x] = sh[1023];
}
__global__ void k_scan23() {   // every block redundantly scans the 98 partials
    __shared__ int sh[128];
    int t = threadIdx.x;
    sh[t] = (t < NBLK) ? d_bsum[t] : 0;
    __syncthreads();
    for (int off = 1; off < 128; off <<= 1) {
        int u = (t >= off) ? sh[t - off] : 0;
        __syncthreads();
        sh[t] += u;
        __syncthreads();
    }
    for (int q = 0; q < 2; q++) {
        int idx = blockIdx.x * 256 + q * 128 + t;
        if (idx < NN) {
            int blk = idx >> 10;
            int boff = (blk > 0) ? sh[blk - 1] : 0;
            d_start[idx] += boff;
        }
    }
}
__global__ void k_fill(const int* __restrict__ src, const int* __restrict__ dst) {
    int e = blockIdx.x * blockDim.x + threadIdx.x;
    if (e >= NE) return;
    int d = dst[e];
    int p = atomicAdd(&d_start[d], 1);   // start[] becomes END pointers
    d_csr[p] = src[e];
}

// ---------------- fp16 GEMM, cp.async double-buffered; fp32 G output ----------
// G32 = dis[row] * (A @ W); A always fp16 (d_X16 or d_H16)
// mode 0: W = W0 [C x C]; mode 1: W = [Wa | Wb] column-concat
__device__ __forceinline__ void issue_tile(int t, const __half* __restrict__ A,
                                           uint32_t sa_u32, int tid) {
    const int i0 = t * TM;
    const int rowlim = NN - i0;
    #pragma unroll
    for (int it = 0; it < 13; it++) {
        int q = it * 256 + tid;
        if (q < TM * 25) {
            int r = q / 25, c4 = (q % 25) * 4;
            int ok = (r < rowlim);
            const __half* src = &A[(size_t)(i0 + (ok ? r : 0)) * C + c4];
            cp_async8(sa_u32 + (uint32_t)(r * WS + (c4 >> 1)) * 4, src, ok ? 8 : 0);
        }
    }
}

__global__ void __launch_bounds__(GEMM_THREADS, 2)
k_gemm(const __half* __restrict__ A, const float* __restrict__ W0,
       const float* __restrict__ Wa, const float* __restrict__ Wb, int mode) {
    extern __shared__ uint32_t sm[];
    const int tid = threadIdx.x, wid = tid >> 5, lane = tid & 31;
    const int g = lane >> 2, tg = lane & 3;
    const uint32_t smb = (uint32_t)__cvta_generic_to_shared(sm);

    for (int i = tid; i < SM_WORDS; i += GEMM_THREADS) sm[i] = 0;
    __syncthreads();   // zero done before any cp.async writes

    // stage W -> fp16; layout B[n][kword]
    for (int idx = tid; idx < C * C; idx += GEMM_THREADS) {
        int k = idx / C, n = idx % C;
        float w = (mode == 0) ? W0[idx]
                              : ((n < OC) ? Wa[k * OC + n] : Wb[k * OC + (n - OC)]);
        ((__half*)(sm + SB))[(n * WS + (k >> 1)) * 2 + (k & 1)] = __float2half_rn(w);
    }

    const int r0 = wid * 16;   // 8 warps x 16 rows = 128
    const int stride = GEMM_GRID;
    int t = blockIdx.x;
    int buf = 0;               // buffer holding tile t
    if (t < NTILES) issue_tile(t, A, smb + SA0 * 4, tid);
    CP_COMMIT();

    for (; t < NTILES; t += stride) {
        int tn = t + stride;
        if (tn < NTILES)
            issue_tile(tn, A, smb + (buf ? SA0 : SA1) * 4, tid);
        CP_COMMIT();
        CP_WAIT1();            // oldest group (tile t) complete
        __syncthreads();       // also covers W staging on first iteration

        const uint32_t* sa = sm + (buf ? SA1 : SA0);

        float acc[13][4];
        #pragma unroll
        for (int nt = 0; nt < 13; nt++)
            #pragma unroll
            for (int q = 0; q < 4; q++) acc[nt][q] = 0.f;

        #pragma unroll
        for (int kt = 0; kt < 7; kt++) {
            const int kw = kt * 8;
            uint32_t a[4];
            a[0] = sa[(r0 + g) * WS + kw + tg];
            a[1] = sa[(r0 + g + 8) * WS + kw + tg];
            a[2] = sa[(r0 + g) * WS + kw + 4 + tg];
            a[3] = sa[(r0 + g + 8) * WS + kw + 4 + tg];
            #pragma unroll
            for (int nt = 0; nt < 13; nt++) {
                const int n0 = nt * 8;
                uint32_t b[2];
                b[0] = sm[SB + (n0 + g) * WS + kw + tg];
                b[1] = sm[SB + (n0 + g) * WS + kw + 4 + tg];
                mma_f16(acc[nt], a, b);
            }
        }

        const int i0 = t * TM;
        const int row1 = i0 + r0 + g, row2 = row1 + 8;
        const float s1 = (row1 < NN) ? d_dis[row1] : 0.f;
        const float s2 = (row2 < NN) ? d_dis[row2] : 0.f;
        #pragma unroll
        for (int nt = 0; nt < 13; nt++) {
            const int c = nt * 8 + 2 * tg;
            if (c < C) {
                if (row1 < NN)
                    *(float2*)&d_G32[(size_t)row1 * C + c] =
                        make_float2(s1 * acc[nt][0], s1 * acc[nt][1]);
                if (row2 < NN)
                    *(float2*)&d_G32[(size_t)row2 * C + c] =
                        make_float2(s2 * acc[nt][2], s2 * acc[nt][3]);
            }
        }
        __syncthreads();   // smem reads done before this buffer is refilled
        buf ^= 1;
    }
}

// ---------------- gather: fp32 rows, shfl-batched csr indices ----------------
__global__ void k_gather(int mode, const float* __restrict__ b1,
                         const float* __restrict__ bmu, const float* __restrict__ bls,
                         float* __restrict__ out) {
    int w = (blockIdx.x * blockDim.x + threadIdx.x) >> 5;
    int lane = threadIdx.x & 31;
    if (w >= NN) return;                 // ALL 32 lanes stay (shfl needs them)
    int en = d_start[w];
    int n  = d_cnt[w];
    if (mode == 1 && lane == 0) d_cnt[w] = 0;   // reset for next run (post-read)
    int st = en - n;
    int p4 = lane * 4;
    const bool act = (p4 < C);           // lanes 25-31: index/shfl helpers only

    float4 acc = act ? *(const float4*)&d_G32[(size_t)w * C + p4]
                     : make_float4(0.f, 0.f, 0.f, 0.f);   // self-loop term

    for (int base = 0; base < n; base += 32) {
        int m = n - base; if (m > 32) m = 32;
        int sidx = (lane < m) ? d_csr[st + base + lane] : 0;   // 1 LDG / 32 edges
        for (int j = 0; j < m; j++) {
            int s = __shfl_sync(0xFFFFFFFFu, sidx, j);
            if (act) {
                float4 v = *(const float4*)&d_G32[(size_t)s * C + p4];
                acc.x += v.x; acc.y += v.y; acc.z += v.z; acc.w += v.w;
            }
        }
    }
    if (!act) return;
    float sc = d_dis[w];

    if (mode == 0) {
        float4 bb = *(const float4*)&b1[p4];
        __half2 h0 = __floats2half2_rn(fmaxf(fmaf(sc, acc.x, bb.x), 0.f),
                                       fmaxf(fmaf(sc, acc.y, bb.y), 0.f));
        __half2 h1 = __floats2half2_rn(fmaxf(fmaf(sc, acc.z, bb.z), 0.f),
                                       fmaxf(fmaf(sc, acc.w, bb.w), 0.f));
        uint2 packed;
        packed.x = *reinterpret_cast<uint32_t*>(&h0);
        packed.y = *reinterpret_cast<uint32_t*>(&h1);
        *(uint2*)&d_H16[(size_t)w * C + p4] = packed;
    } else {
        float v[4] = { sc * acc.x, sc * acc.y, sc * acc.z, sc * acc.w };
        #pragma unroll
        for (int q = 0; q < 4; q++) {
            int c = p4 + q;
            if (c < OC) out[(size_t)w * OC + c]                          = v[q] + bmu[c];
            else        out[(size_t)NN * OC + (size_t)w * OC + (c - OC)] = v[q] + bls[c - OC];
        }
    }
}

extern "C" void kernel_launch(void* const* d_in, const int* in_sizes, int n_in,
                              void* d_out, int out_size) {
    const float* x   = (const float*)d_in[0];
    const int*   ei  = (const int*)  d_in[1];
    const float* W1  = (const float*)d_in[2];
    const float* b1  = (const float*)d_in[3];
    const float* Wmu = (const float*)d_in[4];
    const float* bmu = (const float*)d_in[5];
    const float* Wls = (const float*)d_in[6];
    const float* bls = (const float*)d_in[7];
    float* out = (float*)d_out;

    const int* src = ei;
    const int* dst = ei + NE;

    __half* x16_ptr;  cudaGetSymbolAddress((void**)&x16_ptr, d_X16);
    __half* h16_ptr;  cudaGetSymbolAddress((void**)&h16_ptr, d_H16);

    cudaFuncSetAttribute(k_gemm, cudaFuncAttributeMaxDynamicSharedMemorySize, SM_WORDS * 4);

    // CSR build + x->fp16 conversion (fused; d_cnt arrives zeroed)
    k_degcvt<<<(CVT_QUADS + 255) / 256, 256>>>(dst, x);
    k_scan1<<<NBLK, 1024>>>();
    k_scan23<<<(NN + 255) / 256, 128>>>();
    k_fill<<<(NE + 255) / 256, 256>>>(src, dst);

    // layer 1
    k_gemm<<<GEMM_GRID, GEMM_THREADS, SM_WORDS * 4>>>(x16_ptr, W1, nullptr, nullptr, 0);
    k_gather<<<(NN * 32 + 255) / 256, 256>>>(0, b1, nullptr, nullptr, nullptr);

    // layers 2+3 fused (mu | logstd column-concat)
    k_gemm<<<GEMM_GRID, GEMM_THREADS, SM_WORDS * 4>>>(h16_ptr, nullptr, Wmu, Wls, 1);
    k_gather<<<(NN * 32 + 255) / 256, 256>>>(1, nullptr, bmu, bls, out);
}

// round 16
// speedup vs baseline: 1.1128x; 1.1128x over previous
#include <cuda_runtime.h>
#include <cuda_fp16.h>
#include <stdint.h>

#define NN 100000
#define NE 800000
#define C  100
#define OC 50
#define NBLK ((NN + 1023) / 1024)

#define TM 128
#define NTILES ((NN + TM - 1) / TM)
#define GEMM_GRID 296            // 2 CTAs per SM
#define GEMM_THREADS 256

// word stride per row: reads touch words 0..55; WS=60 -> conflict-free frags
#define WS 60
#define SA0 0
#define SA1 (TM * WS)                  // 7680
#define SB  (2 * TM * WS)              // 15360
#define SM_WORDS (SB + 104 * WS)       // 21600 words = 86400 B (2 CTAs/SM)

#define CVT_QUADS (NN * 25)

// ---------------- device globals (scratch; zero-init at load) ----------------
__device__ __align__(16) float d_dis[NN];
__device__ __align__(16) __half d_X16[NN * C];   // x pre-converted to fp16
__device__ __align__(16) __half d_G16[NN * C];
__device__ __align__(16) __half d_H16[NN * C];
__device__ int d_cnt[NN];      // re-zeroed at tail of gather mode 1 each run
__device__ int d_start[NN];    // after k_fill: END pointers
__device__ int d_csr[NE];
__device__ int d_bsum[NBLK + 1];

// ---------------- PTX helpers (baseline, sm_80+) ----------------
__device__ __forceinline__ void mma_f16(float* d, const uint32_t* a, const uint32_t* b) {
    asm volatile(
        "mma.sync.aligned.m16n8k16.row.col.f32.f16.f16.f32 "
        "{%0,%1,%2,%3}, {%4,%5,%6,%7}, {%8,%9}, {%0,%1,%2,%3};"
        : "+f"(d[0]), "+f"(d[1]), "+f"(d[2]), "+f"(d[3])
        : "r"(a[0]), "r"(a[1]), "r"(a[2]), "r"(a[3]), "r"(b[0]), "r"(b[1]));
}
__device__ __forceinline__ void cp_async8(uint32_t saddr, const void* g, int src_sz) {
    asm volatile("cp.async.ca.shared.global [%0], [%1], 8, %2;"
                 :: "r"(saddr), "l"(g), "r"(src_sz));
}
#define CP_COMMIT() asm volatile("cp.async.commit_group;" ::: "memory")
#define CP_WAIT1()  asm volatile("cp.async.wait_group 1;" ::: "memory")

__device__ __forceinline__ __half2 as_h2(uint32_t u) {
    return *reinterpret_cast<__half2*>(&u);
}

// ---------------- CSR build ----------------
__global__ void k_degcvt(const int* __restrict__ dst, const float* __restrict__ x) {
    int i = blockIdx.x * blockDim.x + threadIdx.x;
    if (i < NE) atomicAdd(&d_cnt[dst[i]], 1);    // cnt pre-zeroed
    if (i < CVT_QUADS) {
        int r = i / 25, c4 = (i % 25) * 4;
        float4 v = *(const float4*)&x[(size_t)r * C + c4];
        __half2 h0 = __floats2half2_rn(v.x, v.y);
        __half2 h1 = __floats2half2_rn(v.z, v.w);
        uint2 w2;
        w2.x = *reinterpret_cast<uint32_t*>(&h0);
        w2.y = *reinterpret_cast<uint32_t*>(&h1);
        *(uint2*)&d_X16[(size_t)r * C + c4] = w2;
    }
}
__global__ void k_scan1() {   // block-local exclusive scan + dis = rsqrt(cnt+1)
    __shared__ int sh[1024];
    int i = blockIdx.x * 1024 + threadIdx.x;
    int v = (i < NN) ? d_cnt[i] : 0;
    sh[threadIdx.x] = v;
    __syncthreads();
    for (int off = 1; off < 1024; off <<= 1) {
        int t = (threadIdx.x >= off) ? sh[threadIdx.x - off] : 0;
        __syncthreads();
        sh[threadIdx.x] += t;
        __syncthreads();
    }
    if (i < NN) {
        d_start[i] = sh[threadIdx.x] - v;
        d_dis[i] = rsqrtf((float)v + 1.0f);
    }
    if (threadIdx.x == 1023) d_bsum[blockIdx.x] = sh[1023];
}
__global__ void k_scan23() {   // every block redundantly scans the 98 partials
    __shared__ int sh[128];
    int t = threadIdx.x;
    sh[t] = (t < NBLK) ? d_bsum[t] : 0;
    __syncthreads();
    for (int off = 1; off < 128; off <<= 1) {
        int u = (t >= off) ? sh[t - off] : 0;
        __syncthreads();
        sh[t] += u;
        __syncthreads();
    }
    for (int q = 0; q < 2; q++) {
        int idx = blockIdx.x * 256 + q * 128 + t;
        if (idx < NN) {
            int blk = idx >> 10;
            int boff = (blk > 0) ? sh[blk - 1] : 0;
            d_start[idx] += boff;
        }
    }
}
__global__ void k_fill(const int* __restrict__ src, const int* __restrict__ dst) {
    int e = blockIdx.x * blockDim.x + threadIdx.x;
    if (e >= NE) return;
    int d = dst[e];
    int p = atomicAdd(&d_start[d], 1);   // start[] becomes END pointers
    d_csr[p] = src[e];
}

// ---------------- fp16 GEMM, cp.async double-buffered (round-13 verbatim) ----
// G16 = dis[row] * (A @ W); A always fp16 (d_X16 or d_H16)
// mode 0: W = W0 [C x C]; mode 1: W = [Wa | Wb] column-concat
__device__ __forceinline__ void issue_tile(int t, const __half* __restrict__ A,
                                           uint32_t sa_u32, int tid) {
    const int i0 = t * TM;
    const int rowlim = NN - i0;
    #pragma unroll
    for (int it = 0; it < 13; it++) {
        int q = it * 256 + tid;
        if (q < TM * 25) {
            int r = q / 25, c4 = (q % 25) * 4;
            int ok = (r < rowlim);
            const __half* src = &A[(size_t)(i0 + (ok ? r : 0)) * C + c4];
            cp_async8(sa_u32 + (uint32_t)(r * WS + (c4 >> 1)) * 4, src, ok ? 8 : 0);
        }
    }
}

__global__ void __launch_bounds__(GEMM_THREADS, 2)
k_gemm(const __half* __restrict__ A, const float* __restrict__ W0,
       const float* __restrict__ Wa, const float* __restrict__ Wb, int mode) {
    extern __shared__ uint32_t sm[];
    const int tid = threadIdx.x, wid = tid >> 5, lane = tid & 31;
    const int g = lane >> 2, tg = lane & 3;
    const uint32_t smb = (uint32_t)__cvta_generic_to_shared(sm);

    for (int i = tid; i < SM_WORDS; i += GEMM_THREADS) sm[i] = 0;
    __syncthreads();   // zero done before any cp.async writes

    // stage W -> fp16; layout B[n][kword]
    for (int idx = tid; idx < C * C; idx += GEMM_THREADS) {
        int k = idx / C, n = idx % C;
        float w = (mode == 0) ? W0[idx]
                              : ((n < OC) ? Wa[k * OC + n] : Wb[k * OC + (n - OC)]);
        ((__half*)(sm + SB))[(n * WS + (k >> 1)) * 2 + (k & 1)] = __float2half_rn(w);
    }

    const int r0 = wid * 16;   // 8 warps x 16 rows = 128
    const int stride = GEMM_GRID;
    int t = blockIdx.x;
    int buf = 0;               // buffer holding tile t
    if (t < NTILES) issue_tile(t, A, smb + SA0 * 4, tid);
    CP_COMMIT();

    for (; t < NTILES; t += stride) {
        int tn = t + stride;
        if (tn < NTILES)
            issue_tile(tn, A, smb + (buf ? SA0 : SA1) * 4, tid);
        CP_COMMIT();
        CP_WAIT1();            // oldest group (tile t) complete
        __syncthreads();       // also covers W staging on first iteration

        const uint32_t* sa = sm + (buf ? SA1 : SA0);

        float acc[13][4];
        #pragma unroll
        for (int nt = 0; nt < 13; nt++)
            #pragma unroll
            for (int q = 0; q < 4; q++) acc[nt][q] = 0.f;

        #pragma unroll
        for (int kt = 0; kt < 7; kt++) {
            const int kw = kt * 8;
            uint32_t a[4];
            a[0] = sa[(r0 + g) * WS + kw + tg];
            a[1] = sa[(r0 + g + 8) * WS + kw + tg];
            a[2] = sa[(r0 + g) * WS + kw + 4 + tg];
            a[3] = sa[(r0 + g + 8) * WS + kw + 4 + tg];
            #pragma unroll
            for (int nt = 0; nt < 13; nt++) {
                const int n0 = nt * 8;
                uint32_t b[2];
                b[0] = sm[SB + (n0 + g) * WS + kw + tg];
                b[1] = sm[SB + (n0 + g) * WS + kw + 4 + tg];
                mma_f16(acc[nt], a, b);
            }
        }

        const int i0 = t * TM;
        const int row1 = i0 + r0 + g, row2 = row1 + 8;
        const float s1 = (row1 < NN) ? d_dis[row1] : 0.f;
        const float s2 = (row2 < NN) ? d_dis[row2] : 0.f;
        #pragma unroll
        for (int nt = 0; nt < 13; nt++) {
            const int c = nt * 8 + 2 * tg;
            if (c < C) {
                if (row1 < NN)
                    *(__half2*)&d_G16[(size_t)row1 * C + c] =
                        __floats2half2_rn(s1 * acc[nt][0], s1 * acc[nt][1]);
                if (row2 < NN)
                    *(__half2*)&d_G16[(size_t)row2 * C + c] =
                        __floats2half2_rn(s2 * acc[nt][2], s2 * acc[nt][3]);
            }
        }
        __syncthreads();   // smem reads done before this buffer is refilled
        buf ^= 1;
    }
}

// ---------------- gather: pairwise HADD2 accumulation (single change) --------
__device__ __forceinline__ float4 ldg_h4(const __half* p) {
    uint2 r = *(const uint2*)p;
    float2 f0 = __half22float2(as_h2(r.x));
    float2 f1 = __half22float2(as_h2(r.y));
    return make_float4(f0.x, f0.y, f1.x, f1.y);
}

__global__ void k_gather(int mode, const float* __restrict__ b1,
                         const float* __restrict__ bmu, const float* __restrict__ bls,
                         float* __restrict__ out) {
    int w = (blockIdx.x * blockDim.x + threadIdx.x) >> 5;
    int lane = threadIdx.x & 31;
    if (w >= NN || lane >= 25) return;
    int en = d_start[w];
    int n  = d_cnt[w];
    if (mode == 1 && lane == 0) d_cnt[w] = 0;   // reset for next run (post-read)
    int st = en - n;
    int p4 = lane * 4;

    float4 acc = ldg_h4(&d_G16[(size_t)w * C + p4]);   // self-loop term

    int j = 0;
    for (; j + 2 <= n; j += 2) {                // pair: add rows in fp16 first
        int s0 = d_csr[st + j];
        int s1 = d_csr[st + j + 1];
        uint2 r0 = *(const uint2*)&d_G16[(size_t)s0 * C + p4];
        uint2 r1 = *(const uint2*)&d_G16[(size_t)s1 * C + p4];
        __half2 a0 = __hadd2(as_h2(r0.x), as_h2(r1.x));
        __half2 a1 = __hadd2(as_h2(r0.y), as_h2(r1.y));
        float2 f0 = __half22float2(a0);
        float2 f1 = __half22float2(a1);
        acc.x += f0.x; acc.y += f0.y; acc.z += f1.x; acc.w += f1.y;
    }
    if (j < n) {                                 // odd tail
        int s = d_csr[st + j];
        float4 v = ldg_h4(&d_G16[(size_t)s * C + p4]);
        acc.x += v.x; acc.y += v.y; acc.z += v.z; acc.w += v.w;
    }
    float sc = d_dis[w];

    if (mode == 0) {
        float4 bb = *(const float4*)&b1[p4];
        __half2 h0 = __floats2half2_rn(fmaxf(fmaf(sc, acc.x, bb.x), 0.f),
                                       fmaxf(fmaf(sc, acc.y, bb.y), 0.f));
        __half2 h1 = __floats2half2_rn(fmaxf(fmaf(sc, acc.z, bb.z), 0.f),
                                       fmaxf(fmaf(sc, acc.w, bb.w), 0.f));
        uint2 packed;
        packed.x = *reinterpret_cast<uint32_t*>(&h0);
        packed.y = *reinterpret_cast<uint32_t*>(&h1);
        *(uint2*)&d_H16[(size_t)w * C + p4] = packed;
    } else {
        float v[4] = { sc * acc.x, sc * acc.y, sc * acc.z, sc * acc.w };
        #pragma unroll
        for (int q = 0; q < 4; q++) {
            int c = p4 + q;
            if (c < OC) out[(size_t)w * OC + c]                          = v[q] + bmu[c];
            else        out[(size_t)NN * OC + (size_t)w * OC + (c - OC)] = v[q] + bls[c - OC];
        }
    }
}

extern "C" void kernel_launch(void* const* d_in, const int* in_sizes, int n_in,
                              void* d_out, int out_size) {
    const float* x   = (const float*)d_in[0];
    const int*   ei  = (const int*)  d_in[1];
    const float* W1  = (const float*)d_in[2];
    const float* b1  = (const float*)d_in[3];
    const float* Wmu = (const float*)d_in[4];
    const float* bmu = (const float*)d_in[5];
    const float* Wls = (const float*)d_in[6];
    const float* bls = (const float*)d_in[7];
    float* out = (float*)d_out;

    const int* src = ei;
    const int* dst = ei + NE;

    __half* x16_ptr;  cudaGetSymbolAddress((void**)&x16_ptr, d_X16);
    __half* h16_ptr;  cudaGetSymbolAddress((void**)&h16_ptr, d_H16);

    cudaFuncSetAttribute(k_gemm, cudaFuncAttributeMaxDynamicSharedMemorySize, SM_WORDS * 4);

    // CSR build + x->fp16 conversion (fused; d_cnt arrives zeroed)
    k_degcvt<<<(CVT_QUADS + 255) / 256, 256>>>(dst, x);
    k_scan1<<<NBLK, 1024>>>();
    k_scan23<<<(NN + 255) / 256, 128>>>();
    k_fill<<<(NE + 255) / 256, 256>>>(src, dst);

    // layer 1
    k_gemm<<<GEMM_GRID, GEMM_THREADS, SM_WORDS * 4>>>(x16_ptr, W1, nullptr, nullptr, 0);
    k_gather<<<(NN * 32 + 255) / 256, 256>>>(0, b1, nullptr, nullptr, nullptr);

    // layers 2+3 fused (mu | logstd column-concat)
    k_gemm<<<GEMM_GRID, GEMM_THREADS, SM_WORDS * 4>>>(h16_ptr, nullptr, Wmu, Wls, 1);
    k_gather<<<(NN * 32 + 255) / 256, 256>>>(1, nullptr, bmu, bls, out);
}

// round 17
// speedup vs baseline: 1.1284x; 1.0140x over previous
#include <cuda_runtime.h>
#include <cuda_fp16.h>
#include <stdint.h>

#define NN 100000
#define NE 800000
#define C  100
#define OC 50
#define NBLK ((NN + 1023) / 1024)

#define TM 128
#define NTILES ((NN + TM - 1) / TM)
#define GEMM_GRID 296            // 2 CTAs per SM
#define GEMM_THREADS 256

// word stride per row: reads touch words 0..55; WS=60 -> conflict-free frags
#define WS 60
#define SA0 0
#define SA1 (TM * WS)                  // 7680
#define SB  (2 * TM * WS)              // 15360
#define SM_WORDS (SB + 104 * WS)       // 21600 words = 86400 B (2 CTAs/SM)

#define CVT_QUADS (NN * 25)

// ---------------- device globals (scratch; zero-init at load) ----------------
__device__ __align__(16) float d_dis[NN];
__device__ __align__(16) __half d_X16[NN * C];   // x pre-converted to fp16
__device__ __align__(16) __half d_G16[NN * C];
__device__ __align__(16) __half d_H16[NN * C];
__device__ int d_cnt[NN];      // re-zeroed at tail of gather mode 1 each run
__device__ int d_start[NN];    // after k_fill: END pointers
__device__ int d_csr[NE];
__device__ int d_total;        // re-zeroed at tail of gather mode 1 each run

// ---------------- PTX helpers (baseline, sm_80+) ----------------
__device__ __forceinline__ void mma_f16(float* d, const uint32_t* a, const uint32_t* b) {
    asm volatile(
        "mma.sync.aligned.m16n8k16.row.col.f32.f16.f16.f32 "
        "{%0,%1,%2,%3}, {%4,%5,%6,%7}, {%8,%9}, {%0,%1,%2,%3};"
        : "+f"(d[0]), "+f"(d[1]), "+f"(d[2]), "+f"(d[3])
        : "r"(a[0]), "r"(a[1]), "r"(a[2]), "r"(a[3]), "r"(b[0]), "r"(b[1]));
}
__device__ __forceinline__ void cp_async8(uint32_t saddr, const void* g, int src_sz) {
    asm volatile("cp.async.ca.shared.global [%0], [%1], 8, %2;"
                 :: "r"(saddr), "l"(g), "r"(src_sz));
}
#define CP_COMMIT() asm volatile("cp.async.commit_group;" ::: "memory")
#define CP_WAIT1()  asm volatile("cp.async.wait_group 1;" ::: "memory")

// ---------------- CSR build ----------------
__global__ void k_degcvt(const int* __restrict__ dst, const float* __restrict__ x) {
    int i = blockIdx.x * blockDim.x + threadIdx.x;
    if (i < NE) atomicAdd(&d_cnt[dst[i]], 1);    // cnt pre-zeroed
    if (i < CVT_QUADS) {
        int r = i / 25, c4 = (i % 25) * 4;
        float4 v = *(const float4*)&x[(size_t)r * C + c4];
        __half2 h0 = __floats2half2_rn(v.x, v.y);
        __half2 h1 = __floats2half2_rn(v.z, v.w);
        uint2 w2;
        w2.x = *reinterpret_cast<uint32_t*>(&h0);
        w2.y = *reinterpret_cast<uint32_t*>(&h1);
        *(uint2*)&d_X16[(size_t)r * C + c4] = w2;
    }
}

// single-launch alloc: block scan + one global atomic base; also dis
__global__ void k_alloc() {
    __shared__ int sh[1024];
    __shared__ int sbase;
    int i = blockIdx.x * 1024 + threadIdx.x;
    int v = (i < NN) ? d_cnt[i] : 0;
    sh[threadIdx.x] = v;
    __syncthreads();
    for (int off = 1; off < 1024; off <<= 1) {
        int t = (threadIdx.x >= off) ? sh[threadIdx.x - off] : 0;
        __syncthreads();
        sh[threadIdx.x] += t;
        __syncthreads();
    }
    if (threadIdx.x == 1023) sbase = atomicAdd(&d_total, sh[1023]);
    __syncthreads();
    if (i < NN) {
        d_start[i] = sbase + sh[threadIdx.x] - v;   // exclusive start
        d_dis[i] = rsqrtf((float)v + 1.0f);
    }
}

__global__ void k_fill(const int* __restrict__ src, const int* __restrict__ dst) {
    int e = blockIdx.x * blockDim.x + threadIdx.x;
    if (e >= NE) return;
    int d = dst[e];
    int p = atomicAdd(&d_start[d], 1);   // start[] becomes END pointers
    d_csr[p] = src[e];
}

// ---------------- fp16 GEMM, cp.async double-buffered (round-13 verbatim) ----
// G16 = dis[row] * (A @ W); A always fp16 (d_X16 or d_H16)
// mode 0: W = W0 [C x C]; mode 1: W = [Wa | Wb] column-concat
__device__ __forceinline__ void issue_tile(int t, const __half* __restrict__ A,
                                           uint32_t sa_u32, int tid) {
    const int i0 = t * TM;
    const int rowlim = NN - i0;
    #pragma unroll
    for (int it = 0; it < 13; it++) {
        int q = it * 256 + tid;
        if (q < TM * 25) {
            int r = q / 25, c4 = (q % 25) * 4;
            int ok = (r < rowlim);
            const __half* src = &A[(size_t)(i0 + (ok ? r : 0)) * C + c4];
            cp_async8(sa_u32 + (uint32_t)(r * WS + (c4 >> 1)) * 4, src, ok ? 8 : 0);
        }
    }
}

__global__ void __launch_bounds__(GEMM_THREADS, 2)
k_gemm(const __half* __restrict__ A, const float* __restrict__ W0,
       const float* __restrict__ Wa, const float* __restrict__ Wb, int mode) {
    extern __shared__ uint32_t sm[];
    const int tid = threadIdx.x, wid = tid >> 5, lane = tid & 31;
    const int g = lane >> 2, tg = lane & 3;
    const uint32_t smb = (uint32_t)__cvta_generic_to_shared(sm);

    for (int i = tid; i < SM_WORDS; i += GEMM_THREADS) sm[i] = 0;
    __syncthreads();   // zero done before any cp.async writes

    // stage W -> fp16; layout B[n][kword]
    for (int idx = tid; idx < C * C; idx += GEMM_THREADS) {
        int k = idx / C, n = idx % C;
        float w = (mode == 0) ? W0[idx]
                              : ((n < OC) ? Wa[k * OC + n] : Wb[k * OC + (n - OC)]);
        ((__half*)(sm + SB))[(n * WS + (k >> 1)) * 2 + (k & 1)] = __float2half_rn(w);
    }

    const int r0 = wid * 16;   // 8 warps x 16 rows = 128
    const int stride = GEMM_GRID;
    int t = blockIdx.x;
    int buf = 0;               // buffer holding tile t
    if (t < NTILES) issue_tile(t, A, smb + SA0 * 4, tid);
    CP_COMMIT();

    for (; t < NTILES; t += stride) {
        int tn = t + stride;
        if (tn < NTILES)
            issue_tile(tn, A, smb + (buf ? SA0 : SA1) * 4, tid);
        CP_COMMIT();
        CP_WAIT1();            // oldest group (tile t) complete
        __syncthreads();       // also covers W staging on first iteration

        const uint32_t* sa = sm + (buf ? SA1 : SA0);

        float acc[13][4];
        #pragma unroll
        for (int nt = 0; nt < 13; nt++)
            #pragma unroll
            for (int q = 0; q < 4; q++) acc[nt][q] = 0.f;

        #pragma unroll
        for (int kt = 0; kt < 7; kt++) {
            const int kw = kt * 8;
            uint32_t a[4];
            a[0] = sa[(r0 + g) * WS + kw + tg];
            a[1] = sa[(r0 + g + 8) * WS + kw + tg];
            a[2] = sa[(r0 + g) * WS + kw + 4 + tg];
            a[3] = sa[(r0 + g + 8) * WS + kw + 4 + tg];
            #pragma unroll
            for (int nt = 0; nt < 13; nt++) {
                const int n0 = nt * 8;
                uint32_t b[2];
                b[0] = sm[SB + (n0 + g) * WS + kw + tg];
                b[1] = sm[SB + (n0 + g) * WS + kw + 4 + tg];
                mma_f16(acc[nt], a, b);
            }
        }

        const int i0 = t * TM;
        const int row1 = i0 + r0 + g, row2 = row1 + 8;
        const float s1 = (row1 < NN) ? d_dis[row1] : 0.f;
        const float s2 = (row2 < NN) ? d_dis[row2] : 0.f;
        #pragma unroll
        for (int nt = 0; nt < 13; nt++) {
            const int c = nt * 8 + 2 * tg;
            if (c < C) {
                if (row1 < NN)
                    *(__half2*)&d_G16[(size_t)row1 * C + c] =
                        __floats2half2_rn(s1 * acc[nt][0], s1 * acc[nt][1]);
                if (row2 < NN)
                    *(__half2*)&d_G16[(size_t)row2 * C + c] =
                        __floats2half2_rn(s2 * acc[nt][2], s2 * acc[nt][3]);
            }
        }
        __syncthreads();   // smem reads done before this buffer is refilled
        buf ^= 1;
    }
}

// ---------------- gather + epilogues (round-13 verbatim) ----------------
__device__ __forceinline__ float4 ldg_h4(const __half* p) {
    uint2 r = *(const uint2*)p;
    __half2 a = *reinterpret_cast<__half2*>(&r.x);
    __half2 b = *reinterpret_cast<__half2*>(&r.y);
    float2 f0 = __half22float2(a), f1 = __half22float2(b);
    return make_float4(f0.x, f0.y, f1.x, f1.y);
}

__global__ void k_gather(int mode, const float* __restrict__ b1,
                         const float* __restrict__ bmu, const float* __restrict__ bls,
                         float* __restrict__ out) {
    int w = (blockIdx.x * blockDim.x + threadIdx.x) >> 5;
    int lane = threadIdx.x & 31;
    if (mode == 1 && blockIdx.x == 0 && threadIdx.x == 0) d_total = 0;  // reset
    if (w >= NN || lane >= 25) return;
    int en = d_start[w];
    int n  = d_cnt[w];
    if (mode == 1 && lane == 0) d_cnt[w] = 0;   // reset for next run (post-read)
    int st = en - n;
    int p4 = lane * 4;

    float4 acc = ldg_h4(&d_G16[(size_t)w * C + p4]);   // self-loop term
    for (int j = 0; j < n; j++) {
        int s = d_csr[st + j];
        float4 v = ldg_h4(&d_G16[(size_t)s * C + p4]);
        acc.x += v.x; acc.y += v.y; acc.z += v.z; acc.w += v.w;
    }
    float sc = d_dis[w];

    if (mode == 0) {
        float4 bb = *(const float4*)&b1[p4];
        __half2 h0 = __floats2half2_rn(fmaxf(fmaf(sc, acc.x, bb.x), 0.f),
                                       fmaxf(fmaf(sc, acc.y, bb.y), 0.f));
        __half2 h1 = __floats2half2_rn(fmaxf(fmaf(sc, acc.z, bb.z), 0.f),
                                       fmaxf(fmaf(sc, acc.w, bb.w), 0.f));
        uint2 packed;
        packed.x = *reinterpret_cast<uint32_t*>(&h0);
        packed.y = *reinterpret_cast<uint32_t*>(&h1);
        *(uint2*)&d_H16[(size_t)w * C + p4] = packed;
    } else {
        float v[4] = { sc * acc.x, sc * acc.y, sc * acc.z, sc * acc.w };
        #pragma unroll
        for (int q = 0; q < 4; q++) {
            int c = p4 + q;
            if (c < OC) out[(size_t)w * OC + c]                          = v[q] + bmu[c];
            else        out[(size_t)NN * OC + (size_t)w * OC + (c - OC)] = v[q] + bls[c - OC];
        }
    }
}

extern "C" void kernel_launch(void* const* d_in, const int* in_sizes, int n_in,
                              void* d_out, int out_size) {
    const float* x   = (const float*)d_in[0];
    const int*   ei  = (const int*)  d_in[1];
    const float* W1  = (const float*)d_in[2];
    const float* b1  = (const float*)d_in[3];
    const float* Wmu = (const float*)d_in[4];
    const float* bmu = (const float*)d_in[5];
    const float* Wls = (const float*)d_in[6];
    const float* bls = (const float*)d_in[7];
    float* out = (float*)d_out;

    const int* src = ei;
    const int* dst = ei + NE;

    __half* x16_ptr;  cudaGetSymbolAddress((void**)&x16_ptr, d_X16);
    __half* h16_ptr;  cudaGetSymbolAddress((void**)&h16_ptr, d_H16);

    cudaFuncSetAttribute(k_gemm, cudaFuncAttributeMaxDynamicSharedMemorySize, SM_WORDS * 4);

    // CSR build: counts + x->fp16, single-launch alloc, fill
    k_degcvt<<<(CVT_QUADS + 255) / 256, 256>>>(dst, x);
    k_alloc<<<NBLK, 1024>>>();
    k_fill<<<(NE + 255) / 256, 256>>>(src, dst);

    // layer 1
    k_gemm<<<GEMM_GRID, GEMM_THREADS, SM_WORDS * 4>>>(x16_ptr, W1, nullptr, nullptr, 0);
    k_gather<<<(NN * 32 + 255) / 256, 256>>>(0, b1, nullptr, nullptr, nullptr);

    // layers 2+3 fused (mu | logstd column-concat)
    k_gemm<<<GEMM_GRID, GEMM_THREADS, SM_WORDS * 4>>>(h16_ptr, nullptr, Wmu, Wls, 1);
    k_gather<<<(NN * 32 + 255) / 256, 256>>>(1, nullptr, bmu, bls, out);
}